// round 3
// baseline (speedup 1.0000x reference)
#include <cuda_runtime.h>
#include <cuda_bf16.h>
#include <math.h>

#define NN 50000
#define CC 128
#define EE 800000

typedef unsigned long long u64;

// ---------------- scratch (static device globals; no allocation) ----------
__device__ float g_m[NN * CC];        // state @ W_lin^T
__device__ float g_prop[NN * CC];     // segment-sum result
__device__ float g_sA[NN * CC];       // state ping
__device__ float g_sB[NN * CC];       // state pong
__device__ float g_gi[NN * 3 * CC];   // input gates
__device__ float g_gh[NN * 3 * CC];   // hidden gates
__device__ int   g_cnt[NN];           // degree counts / fill cursor
__device__ int   g_rowptr[NN + 1];    // CSR row pointers (by dst)
__device__ int   g_perm[EE];          // src node per CSR slot
__device__ int   g_bsum[64];          // scan block sums

// ---------------- f32x2 packed-FMA helpers ---------------------------------
__device__ __forceinline__ u64 fma2(u64 a, u64 b, u64 c) {
    u64 d;
    asm("fma.rn.f32x2 %0, %1, %2, %3;" : "=l"(d) : "l"(a), "l"(b), "l"(c));
    return d;
}
__device__ __forceinline__ u64 pack_dup(float x) {
    u64 r;
    asm("mov.b64 %0, {%1, %1};" : "=l"(r) : "f"(x));
    return r;
}
__device__ __forceinline__ float2 unpack2(u64 a) {
    float2 o;
    asm("mov.b64 {%0, %1}, %2;" : "=f"(o.x), "=f"(o.y) : "l"(a));
    return o;
}

// ---------------- small utility kernels -----------------------------------
__global__ void zero_int(int* p, int n) {
    int i = blockIdx.x * blockDim.x + threadIdx.x;
    if (i < n) p[i] = 0;
}

__global__ void count_k(const int* __restrict__ dst, int* __restrict__ cnt) {
    int e = blockIdx.x * blockDim.x + threadIdx.x;
    if (e < EE) {
        int d = dst[e];
        d = min(max(d, 0), NN - 1);
        atomicAdd(&cnt[d], 1);
    }
}

__global__ void scan_block(const int* __restrict__ cnt, int* __restrict__ excl,
                           int* __restrict__ bsum, int n) {
    __shared__ int sm[1024];
    int t = threadIdx.x;
    int g = blockIdx.x * 1024 + t;
    int v = (g < n) ? cnt[g] : 0;
    sm[t] = v;
    __syncthreads();
    for (int off = 1; off < 1024; off <<= 1) {
        int tv = 0;
        if (t >= off) tv = sm[t - off];
        __syncthreads();
        if (t >= off) sm[t] += tv;
        __syncthreads();
    }
    if (g < n) excl[g] = sm[t] - v;
    if (t == 1023) bsum[blockIdx.x] = sm[1023];
}

__global__ void scan_sums(int* bsum, int nb) {
    int run = 0;
    for (int i = 0; i < nb; i++) { int t = bsum[i]; bsum[i] = run; run += t; }
}

__global__ void add_off(int* __restrict__ rowptr, const int* __restrict__ bsum, int n) {
    int g = blockIdx.x * blockDim.x + threadIdx.x;
    if (g < n) rowptr[g] += bsum[g >> 10];
    if (g == 0) rowptr[n] = EE;
}

__global__ void fill_k(const int* __restrict__ src, const int* __restrict__ dst,
                       const int* __restrict__ rowptr, int* __restrict__ cur,
                       int* __restrict__ perm) {
    int e = blockIdx.x * blockDim.x + threadIdx.x;
    if (e < EE) {
        int d = dst[e];
        d = min(max(d, 0), NN - 1);
        int s = src[e];
        s = min(max(s, 0), NN - 1);
        int pos = rowptr[d] + atomicAdd(&cur[d], 1);
        if (pos >= 0 && pos < EE) perm[pos] = s;
    }
}

// ---------------- GEMM: Y[nrows,M] = X[nrows,128] @ W[M,128]^T (+bias) ----
// BM=128 rows, BN=64 cols per block, 256 threads, 8x4 micro-tile via f32x2
// packed FMA. Ws is transposed to [k][c] so column-pairs are 64-bit LDS.
#define WSS 66
#define SMEM_GEMM ((128 * 128 + 128 * WSS) * 4)

__global__ __launch_bounds__(256, 2)
void gemm_xwt(const float* __restrict__ X, const float* __restrict__ W,
              const float* __restrict__ bias, float* __restrict__ Y,
              int nrows, int M) {
    extern __shared__ float shbuf[];
    float* Xs = shbuf;                 // [128][128]  Xs[r][k]
    float* Ws = shbuf + 128 * 128;     // [128][66]   Ws[k][c]

    int row0 = blockIdx.x * 128;
    int col0 = blockIdx.y * 64;
    int tid = threadIdx.x;

    // load X tile (128x128 floats = 4096 float4, 16 per thread), zero-pad OOB rows
    {
        const float4* Xg = (const float4*)X;
        #pragma unroll
        for (int i = 0; i < 16; i++) {
            int idx = tid + i * 256;       // 0..4095
            int r = idx >> 5;
            int c4 = idx & 31;
            float4 v = make_float4(0.f, 0.f, 0.f, 0.f);
            if (row0 + r < nrows) v = Xg[(size_t)(row0 + r) * 32 + c4];
            *(float4*)&Xs[r * 128 + c4 * 4] = v;
        }
    }
    // load W tile (64 cols x 128 k) transposed into Ws[k][c]
    // mapping: c = idx & 63, k4 = idx >> 6  -> conflict-free smem stores
    {
        const float4* Wg = (const float4*)W;
        #pragma unroll
        for (int i = 0; i < 8; i++) {
            int idx = tid + i * 256;       // 0..2047
            int c  = idx & 63;
            int k4 = idx >> 6;             // 0..31
            float4 v = Wg[(size_t)(col0 + c) * 32 + k4];
            Ws[(k4 * 4 + 0) * WSS + c] = v.x;
            Ws[(k4 * 4 + 1) * WSS + c] = v.y;
            Ws[(k4 * 4 + 2) * WSS + c] = v.z;
            Ws[(k4 * 4 + 3) * WSS + c] = v.w;
        }
    }
    __syncthreads();

    int tx = tid & 15;   // -> cols col0 + 4*tx + {0..3}
    int ty = tid >> 4;   // -> rows row0 + 8*ty + {0..7}

    u64 accp[8][2];      // 8 rows x 2 col-pairs (4 cols)
    #pragma unroll
    for (int u = 0; u < 8; u++) { accp[u][0] = 0ull; accp[u][1] = 0ull; }

    const float* xb = &Xs[(8 * ty) * 128];
    const float* wb = &Ws[4 * tx];

    #pragma unroll 8
    for (int k = 0; k < 128; k += 4) {
        float4 xv[8];
        #pragma unroll
        for (int u = 0; u < 8; u++) xv[u] = *(const float4*)&xb[u * 128 + k];
        u64 wv[4][2];
        #pragma unroll
        for (int kk = 0; kk < 4; kk++) {
            wv[kk][0] = *(const u64*)&wb[(k + kk) * WSS + 0];
            wv[kk][1] = *(const u64*)&wb[(k + kk) * WSS + 2];
        }
        #pragma unroll
        for (int kk = 0; kk < 4; kk++) {
            #pragma unroll
            for (int u = 0; u < 8; u++) {
                float xs = (kk == 0) ? xv[u].x : (kk == 1) ? xv[u].y
                          : (kk == 2) ? xv[u].z : xv[u].w;
                u64 x2 = pack_dup(xs);
                accp[u][0] = fma2(x2, wv[kk][0], accp[u][0]);
                accp[u][1] = fma2(x2, wv[kk][1], accp[u][1]);
            }
        }
    }

    float4 b4 = make_float4(0.f, 0.f, 0.f, 0.f);
    if (bias) b4 = *(const float4*)&bias[col0 + 4 * tx];

    #pragma unroll
    for (int u = 0; u < 8; u++) {
        int r = row0 + 8 * ty + u;
        if (r < nrows) {
            float2 p0 = unpack2(accp[u][0]);
            float2 p1 = unpack2(accp[u][1]);
            float4 o;
            o.x = p0.x + b4.x;
            o.y = p0.y + b4.y;
            o.z = p1.x + b4.z;
            o.w = p1.y + b4.w;
            *(float4*)&Y[(size_t)r * M + col0 + 4 * tx] = o;
        }
    }
}

// ---------------- aggregation: prop[i,:] = sum over in-edges m[src,:] -----
__global__ void aggregate(const float* __restrict__ m, const int* __restrict__ rowptr,
                          const int* __restrict__ perm, float* __restrict__ prop) {
    int i = blockIdx.x;
    int c = threadIdx.x;
    int s0 = rowptr[i], s1 = rowptr[i + 1];
    float a0 = 0.f, a1 = 0.f, a2 = 0.f, a3 = 0.f;
    int e = s0;
    for (; e + 3 < s1; e += 4) {
        int p0 = perm[e], p1 = perm[e + 1], p2 = perm[e + 2], p3 = perm[e + 3];
        a0 += m[p0 * 128 + c];
        a1 += m[p1 * 128 + c];
        a2 += m[p2 * 128 + c];
        a3 += m[p3 * 128 + c];
    }
    for (; e < s1; e++) a0 += m[perm[e] * 128 + c];
    prop[i * 128 + c] = (a0 + a1) + (a2 + a3);
}

// ---------------- GRU elementwise ------------------------------------------
__global__ void gru_k(const float* __restrict__ gi, const float* __restrict__ gh,
                      const float* __restrict__ h, float* __restrict__ out, int n) {
    int idx = blockIdx.x * blockDim.x + threadIdx.x;
    if (idx >= n) return;
    int i = idx >> 7;
    int c = idx & 127;
    const float* gir = gi + (size_t)i * 384;
    const float* ghr = gh + (size_t)i * 384;
    float ir = gir[c], iz = gir[c + 128], in_ = gir[c + 256];
    float hr = ghr[c], hz = ghr[c + 128], hn = ghr[c + 256];
    float r = 1.f / (1.f + expf(-(ir + hr)));
    float z = 1.f / (1.f + expf(-(iz + hz)));
    float nval = tanhf(in_ + r * hn);
    out[idx] = (1.f - z) * nval + z * h[idx];
}

// ---------------- launcher --------------------------------------------------
extern "C" void kernel_launch(void* const* d_in, const int* in_sizes, int n_in,
                              void* d_out, int out_size) {
    const float* x     = (const float*)d_in[0];
    const int*   ei    = (const int*)d_in[1];   // int32 (JAX x64 disabled)
    const float* W_lin = (const float*)d_in[2];
    const float* W_ih  = (const float*)d_in[3];
    const float* W_hh  = (const float*)d_in[4];
    const float* b_ih  = (const float*)d_in[5];
    const float* b_hh  = (const float*)d_in[6];
    float* out = (float*)d_out;

    const int* src = ei;
    const int* dst = ei + EE;

    float *m_, *prop_, *sA_, *sB_, *gi_, *gh_;
    int *cnt_, *rp_, *perm_, *bsum_;
    cudaGetSymbolAddress((void**)&m_,    g_m);
    cudaGetSymbolAddress((void**)&prop_, g_prop);
    cudaGetSymbolAddress((void**)&sA_,   g_sA);
    cudaGetSymbolAddress((void**)&sB_,   g_sB);
    cudaGetSymbolAddress((void**)&gi_,   g_gi);
    cudaGetSymbolAddress((void**)&gh_,   g_gh);
    cudaGetSymbolAddress((void**)&cnt_,  g_cnt);
    cudaGetSymbolAddress((void**)&rp_,   g_rowptr);
    cudaGetSymbolAddress((void**)&perm_, g_perm);
    cudaGetSymbolAddress((void**)&bsum_, g_bsum);

    cudaFuncSetAttribute(gemm_xwt, cudaFuncAttributeMaxDynamicSharedMemorySize, SMEM_GEMM);

    const int NB_SCAN = (NN + 1023) / 1024;   // 49

    // ---- build CSR (edge structure fixed across steps) ----
    zero_int <<<(NN + 255) / 256, 256>>>(cnt_, NN);
    count_k  <<<(EE + 255) / 256, 256>>>(dst, cnt_);
    scan_block<<<NB_SCAN, 1024>>>(cnt_, rp_, bsum_, NN);
    scan_sums <<<1, 1>>>(bsum_, NB_SCAN);
    add_off   <<<(NN + 255) / 256, 256>>>(rp_, bsum_, NN);
    zero_int  <<<(NN + 255) / 256, 256>>>(cnt_, NN);
    fill_k    <<<(EE + 255) / 256, 256>>>(src, dst, rp_, cnt_, perm_);

    // ---- 3 propagation steps ----
    dim3 g128((NN + 127) / 128, 128 / 64);
    dim3 g384((NN + 127) / 128, 384 / 64);

    const float* sin = x;
    for (int step = 0; step < 3; step++) {
        float* sout = (step == 2) ? out : ((step == 0) ? sA_ : sB_);

        gemm_xwt<<<g128, 256, SMEM_GEMM>>>(sin, W_lin, nullptr, m_, NN, 128);
        aggregate<<<NN, 128>>>(m_, rp_, perm_, prop_);
        gemm_xwt<<<g384, 256, SMEM_GEMM>>>(prop_, W_ih, b_ih, gi_, NN, 384);
        gemm_xwt<<<g384, 256, SMEM_GEMM>>>(sin, W_hh, b_hh, gh_, NN, 384);
        gru_k<<<(NN * CC + 255) / 256, 256>>>(gi_, gh_, sin, sout, NN * CC);

        sin = sout;
    }
}

// round 5
// speedup vs baseline: 1.4058x; 1.4058x over previous
#include <cuda_runtime.h>
#include <cuda_bf16.h>
#include <mma.h>
#include <cstdint>
#include <math.h>

using namespace nvcuda;

#define NN 50000
#define CC 128
#define EE 800000
#define NPAD 50048            // 782 * 64

// ---------------- scratch (static device globals; no allocation) ----------
__device__ float g_m[NPAD * CC];       // state @ W_lin^T (padded rows)
__device__ float g_prop[NN * CC];      // segment-sum result
__device__ float g_sA[NN * CC];        // state ping
__device__ float g_sB[NN * CC];        // state pong
__device__ float g_gi[NPAD * 3 * CC];  // input gates (padded)
__device__ float g_gh[NPAD * 3 * CC];  // hidden gates (padded)
__device__ int   g_cnt[NN];
__device__ int   g_rowptr[NN + 1];
__device__ int   g_perm[EE];
__device__ int   g_bsum[64];

// bf16 split buffers (padded rows; pad region zeroed once)
__device__ __nv_bfloat16 g_sxh[NPAD * CC];
__device__ __nv_bfloat16 g_sxl[NPAD * CC];
__device__ __nv_bfloat16 g_sph[NPAD * CC];
__device__ __nv_bfloat16 g_spl[NPAD * CC];
__device__ __nv_bfloat16 g_wlh[128 * CC];
__device__ __nv_bfloat16 g_wll[128 * CC];
__device__ __nv_bfloat16 g_wihh[384 * CC];
__device__ __nv_bfloat16 g_wihl[384 * CC];
__device__ __nv_bfloat16 g_whhh[384 * CC];
__device__ __nv_bfloat16 g_whhl[384 * CC];

// ---------------- small utility kernels -----------------------------------
__global__ void zero_int(int* p, int n) {
    int i = blockIdx.x * blockDim.x + threadIdx.x;
    if (i < n) p[i] = 0;
}

__global__ void zero_pad_bf16(__nv_bfloat16* a, __nv_bfloat16* b,
                              __nv_bfloat16* c, __nv_bfloat16* d) {
    int i = blockIdx.x * blockDim.x + threadIdx.x;
    int n = (NPAD - NN) * CC;
    if (i < n) {
        int off = NN * CC + i;
        a[off] = __float2bfloat16(0.f);
        b[off] = __float2bfloat16(0.f);
        c[off] = __float2bfloat16(0.f);
        d[off] = __float2bfloat16(0.f);
    }
}

__global__ void count_k(const int* __restrict__ dst, int* __restrict__ cnt) {
    int e = blockIdx.x * blockDim.x + threadIdx.x;
    if (e < EE) {
        int d = dst[e];
        d = min(max(d, 0), NN - 1);
        atomicAdd(&cnt[d], 1);
    }
}

__global__ void scan_block(const int* __restrict__ cnt, int* __restrict__ excl,
                           int* __restrict__ bsum, int n) {
    __shared__ int sm[1024];
    int t = threadIdx.x;
    int g = blockIdx.x * 1024 + t;
    int v = (g < n) ? cnt[g] : 0;
    sm[t] = v;
    __syncthreads();
    for (int off = 1; off < 1024; off <<= 1) {
        int tv = 0;
        if (t >= off) tv = sm[t - off];
        __syncthreads();
        if (t >= off) sm[t] += tv;
        __syncthreads();
    }
    if (g < n) excl[g] = sm[t] - v;
    if (t == 1023) bsum[blockIdx.x] = sm[1023];
}

__global__ void scan_sums(int* bsum, int nb) {
    int run = 0;
    for (int i = 0; i < nb; i++) { int t = bsum[i]; bsum[i] = run; run += t; }
}

__global__ void add_off(int* __restrict__ rowptr, const int* __restrict__ bsum, int n) {
    int g = blockIdx.x * blockDim.x + threadIdx.x;
    if (g < n) rowptr[g] += bsum[g >> 10];
    if (g == 0) rowptr[n] = EE;
}

__global__ void fill_k(const int* __restrict__ src, const int* __restrict__ dst,
                       const int* __restrict__ rowptr, int* __restrict__ cur,
                       int* __restrict__ perm) {
    int e = blockIdx.x * blockDim.x + threadIdx.x;
    if (e < EE) {
        int d = dst[e];
        d = min(max(d, 0), NN - 1);
        int s = src[e];
        s = min(max(s, 0), NN - 1);
        int pos = rowptr[d] + atomicAdd(&cur[d], 1);
        if (pos >= 0 && pos < EE) perm[pos] = s;
    }
}

// ---------------- fp32 -> bf16 hi/lo split ---------------------------------
__global__ void conv_split(const float* __restrict__ x, __nv_bfloat16* __restrict__ hi,
                           __nv_bfloat16* __restrict__ lo, int n4) {
    int i = blockIdx.x * blockDim.x + threadIdx.x;
    if (i >= n4) return;
    float4 v = ((const float4*)x)[i];
    __nv_bfloat16 h0 = __float2bfloat16(v.x);
    __nv_bfloat16 h1 = __float2bfloat16(v.y);
    __nv_bfloat16 h2 = __float2bfloat16(v.z);
    __nv_bfloat16 h3 = __float2bfloat16(v.w);
    __nv_bfloat16 l0 = __float2bfloat16(v.x - __bfloat162float(h0));
    __nv_bfloat16 l1 = __float2bfloat16(v.y - __bfloat162float(h1));
    __nv_bfloat16 l2 = __float2bfloat16(v.z - __bfloat162float(h2));
    __nv_bfloat16 l3 = __float2bfloat16(v.w - __bfloat162float(h3));
    __nv_bfloat162* hp = (__nv_bfloat162*)hi;
    __nv_bfloat162* lp = (__nv_bfloat162*)lo;
    hp[i * 2 + 0] = __nv_bfloat162(h0, h1);
    hp[i * 2 + 1] = __nv_bfloat162(h2, h3);
    lp[i * 2 + 0] = __nv_bfloat162(l0, l1);
    lp[i * 2 + 1] = __nv_bfloat162(l2, l3);
}

// ---------------- wmma split-bf16 GEMM --------------------------------------
// Y[NPAD, M] = A[NPAD,128] @ B[M,128]^T, A = Ah+Al, B = Bh+Bl (drop Al*Bl)
// block 64x64 tile, full K=128 in smem, 4 warps, warp tile 32x32.
#define LDSB 136                              // 128 + 8 bf16 pad
#define GT_SMEM (4 * 64 * LDSB * 2)           // 69632 bytes

__global__ __launch_bounds__(128, 2)
void gemm_tc(const __nv_bfloat16* __restrict__ Ah, const __nv_bfloat16* __restrict__ Al,
             const __nv_bfloat16* __restrict__ Bh, const __nv_bfloat16* __restrict__ Bl,
             float* __restrict__ Y, int M) {
    extern __shared__ __nv_bfloat16 smb[];
    __nv_bfloat16* As_h = smb;
    __nv_bfloat16* As_l = smb + 64 * LDSB;
    __nv_bfloat16* Bs_h = smb + 2 * 64 * LDSB;
    __nv_bfloat16* Bs_l = smb + 3 * 64 * LDSB;

    int row0 = blockIdx.x * 64;
    int col0 = blockIdx.y * 64;
    int t = threadIdx.x;

    // each tile: 64 rows x 16 uint4 (row = 256B); 8 uint4 per thread per tile
    {
        const uint4* gAh = (const uint4*)(Ah + (size_t)row0 * 128);
        const uint4* gAl = (const uint4*)(Al + (size_t)row0 * 128);
        const uint4* gBh = (const uint4*)(Bh + (size_t)col0 * 128);
        const uint4* gBl = (const uint4*)(Bl + (size_t)col0 * 128);
        #pragma unroll
        for (int i = 0; i < 8; i++) {
            int idx = t + i * 128;       // 0..1023
            int r = idx >> 4;
            int c = idx & 15;
            ((uint4*)(As_h + r * LDSB))[c] = gAh[r * 16 + c];
            ((uint4*)(As_l + r * LDSB))[c] = gAl[r * 16 + c];
            ((uint4*)(Bs_h + r * LDSB))[c] = gBh[r * 16 + c];
            ((uint4*)(Bs_l + r * LDSB))[c] = gBl[r * 16 + c];
        }
    }
    __syncthreads();

    int wid = t >> 5;
    int wm = wid >> 1;      // 0..1 -> rows
    int wn = wid & 1;       // 0..1 -> cols

    wmma::fragment<wmma::accumulator, 16, 16, 16, float> acc[2][2];
    #pragma unroll
    for (int i = 0; i < 2; i++)
        #pragma unroll
        for (int j = 0; j < 2; j++) wmma::fill_fragment(acc[i][j], 0.0f);

    #pragma unroll
    for (int ks = 0; ks < 8; ks++) {
        int k0 = ks * 16;
        wmma::fragment<wmma::matrix_a, 16, 16, 16, __nv_bfloat16, wmma::row_major> ah[2], al[2];
        wmma::fragment<wmma::matrix_b, 16, 16, 16, __nv_bfloat16, wmma::col_major> bh[2], bl[2];
        #pragma unroll
        for (int i = 0; i < 2; i++) {
            int rr = wm * 32 + i * 16;
            wmma::load_matrix_sync(ah[i], &As_h[rr * LDSB + k0], LDSB);
            wmma::load_matrix_sync(al[i], &As_l[rr * LDSB + k0], LDSB);
        }
        #pragma unroll
        for (int j = 0; j < 2; j++) {
            int cc = wn * 32 + j * 16;
            wmma::load_matrix_sync(bh[j], &Bs_h[cc * LDSB + k0], LDSB);
            wmma::load_matrix_sync(bl[j], &Bs_l[cc * LDSB + k0], LDSB);
        }
        #pragma unroll
        for (int i = 0; i < 2; i++) {
            #pragma unroll
            for (int j = 0; j < 2; j++) {
                wmma::mma_sync(acc[i][j], ah[i], bh[j], acc[i][j]);
                wmma::mma_sync(acc[i][j], ah[i], bl[j], acc[i][j]);
                wmma::mma_sync(acc[i][j], al[i], bh[j], acc[i][j]);
            }
        }
    }

    #pragma unroll
    for (int i = 0; i < 2; i++) {
        #pragma unroll
        for (int j = 0; j < 2; j++) {
            size_t off = (size_t)(row0 + wm * 32 + i * 16) * M + col0 + wn * 32 + j * 16;
            wmma::store_matrix_sync(&Y[off], acc[i][j], M, wmma::mem_row_major);
        }
    }
}

// ---------------- aggregation: prop[i,:] = sum over in-edges m[src,:] -----
__global__ void aggregate(const float* __restrict__ m, const int* __restrict__ rowptr,
                          const int* __restrict__ perm, float* __restrict__ prop) {
    int i = blockIdx.x;
    int c = threadIdx.x;
    int s0 = rowptr[i], s1 = rowptr[i + 1];
    float a0 = 0.f, a1 = 0.f, a2 = 0.f, a3 = 0.f;
    int e = s0;
    for (; e + 3 < s1; e += 4) {
        int p0 = perm[e], p1 = perm[e + 1], p2 = perm[e + 2], p3 = perm[e + 3];
        a0 += m[p0 * 128 + c];
        a1 += m[p1 * 128 + c];
        a2 += m[p2 * 128 + c];
        a3 += m[p3 * 128 + c];
    }
    for (; e < s1; e++) a0 += m[perm[e] * 128 + c];
    prop[i * 128 + c] = (a0 + a1) + (a2 + a3);
}

// ---------------- GRU elementwise (adds biases here) -----------------------
__global__ void gru_k(const float* __restrict__ gi, const float* __restrict__ gh,
                      const float* __restrict__ b_ih, const float* __restrict__ b_hh,
                      const float* __restrict__ h, float* __restrict__ out, int n) {
    int idx = blockIdx.x * blockDim.x + threadIdx.x;
    if (idx >= n) return;
    int i = idx >> 7;
    int c = idx & 127;
    const float* gir = gi + (size_t)i * 384;
    const float* ghr = gh + (size_t)i * 384;
    float ir = gir[c] + b_ih[c];
    float iz = gir[c + 128] + b_ih[c + 128];
    float in_ = gir[c + 256] + b_ih[c + 256];
    float hr = ghr[c] + b_hh[c];
    float hz = ghr[c + 128] + b_hh[c + 128];
    float hn = ghr[c + 256] + b_hh[c + 256];
    float r = 1.f / (1.f + expf(-(ir + hr)));
    float z = 1.f / (1.f + expf(-(iz + hz)));
    float nval = tanhf(in_ + r * hn);
    out[idx] = (1.f - z) * nval + z * h[idx];
}

// ---------------- launcher --------------------------------------------------
extern "C" void kernel_launch(void* const* d_in, const int* in_sizes, int n_in,
                              void* d_out, int out_size) {
    const float* x     = (const float*)d_in[0];
    const int*   ei    = (const int*)d_in[1];   // int32 (JAX x64 disabled)
    const float* W_lin = (const float*)d_in[2];
    const float* W_ih  = (const float*)d_in[3];
    const float* W_hh  = (const float*)d_in[4];
    const float* b_ih  = (const float*)d_in[5];
    const float* b_hh  = (const float*)d_in[6];
    float* out = (float*)d_out;

    const int* src = ei;
    const int* dst = ei + EE;

    float *m_, *prop_, *sA_, *sB_, *gi_, *gh_;
    int *cnt_, *rp_, *perm_, *bsum_;
    __nv_bfloat16 *sxh_, *sxl_, *sph_, *spl_, *wlh_, *wll_, *wihh_, *wihl_, *whhh_, *whhl_;
    cudaGetSymbolAddress((void**)&m_,    g_m);
    cudaGetSymbolAddress((void**)&prop_, g_prop);
    cudaGetSymbolAddress((void**)&sA_,   g_sA);
    cudaGetSymbolAddress((void**)&sB_,   g_sB);
    cudaGetSymbolAddress((void**)&gi_,   g_gi);
    cudaGetSymbolAddress((void**)&gh_,   g_gh);
    cudaGetSymbolAddress((void**)&cnt_,  g_cnt);
    cudaGetSymbolAddress((void**)&rp_,   g_rowptr);
    cudaGetSymbolAddress((void**)&perm_, g_perm);
    cudaGetSymbolAddress((void**)&bsum_, g_bsum);
    cudaGetSymbolAddress((void**)&sxh_,  g_sxh);
    cudaGetSymbolAddress((void**)&sxl_,  g_sxl);
    cudaGetSymbolAddress((void**)&sph_,  g_sph);
    cudaGetSymbolAddress((void**)&spl_,  g_spl);
    cudaGetSymbolAddress((void**)&wlh_,  g_wlh);
    cudaGetSymbolAddress((void**)&wll_,  g_wll);
    cudaGetSymbolAddress((void**)&wihh_, g_wihh);
    cudaGetSymbolAddress((void**)&wihl_, g_wihl);
    cudaGetSymbolAddress((void**)&whhh_, g_whhh);
    cudaGetSymbolAddress((void**)&whhl_, g_whhl);

    cudaFuncSetAttribute(gemm_tc, cudaFuncAttributeMaxDynamicSharedMemorySize, GT_SMEM);

    const int NB_SCAN = (NN + 1023) / 1024;   // 49

    // ---- build CSR (edge structure fixed across steps) ----
    zero_int <<<(NN + 255) / 256, 256>>>(cnt_, NN);
    count_k  <<<(EE + 255) / 256, 256>>>(dst, cnt_);
    scan_block<<<NB_SCAN, 1024>>>(cnt_, rp_, bsum_, NN);
    scan_sums <<<1, 1>>>(bsum_, NB_SCAN);
    add_off   <<<(NN + 255) / 256, 256>>>(rp_, bsum_, NN);
    zero_int  <<<(NN + 255) / 256, 256>>>(cnt_, NN);
    fill_k    <<<(EE + 255) / 256, 256>>>(src, dst, rp_, cnt_, perm_);

    // ---- zero pad region of split buffers; split weights once ----
    zero_pad_bf16<<<((NPAD - NN) * CC + 255) / 256, 256>>>(sxh_, sxl_, sph_, spl_);
    conv_split<<<(128 * CC / 4 + 255) / 256, 256>>>(W_lin, wlh_, wll_, 128 * CC / 4);
    conv_split<<<(384 * CC / 4 + 255) / 256, 256>>>(W_ih, wihh_, wihl_, 384 * CC / 4);
    conv_split<<<(384 * CC / 4 + 255) / 256, 256>>>(W_hh, whhh_, whhl_, 384 * CC / 4);

    // ---- 3 propagation steps ----
    const int RT = NPAD / 64;          // 782 row tiles
    dim3 gm(RT, 128 / 64);             // 782 x 2
    dim3 gg(RT, 384 / 64);             // 782 x 6
    const int N4 = NN * CC / 4;

    const float* sin = x;
    for (int step = 0; step < 3; step++) {
        float* sout = (step == 2) ? out : ((step == 0) ? sA_ : sB_);

        conv_split<<<(N4 + 255) / 256, 256>>>(sin, sxh_, sxl_, N4);
        gemm_tc<<<gm, 128, GT_SMEM>>>(sxh_, sxl_, wlh_, wll_, m_, 128);
        aggregate<<<NN, 128>>>(m_, rp_, perm_, prop_);
        conv_split<<<(N4 + 255) / 256, 256>>>(prop_, sph_, spl_, N4);
        gemm_tc<<<gg, 128, GT_SMEM>>>(sph_, spl_, wihh_, wihl_, gi_, 384);
        gemm_tc<<<gg, 128, GT_SMEM>>>(sxh_, sxl_, whhh_, whhl_, gh_, 384);
        gru_k<<<(NN * CC + 255) / 256, 256>>>(gi_, gh_, b_ih, b_hh, sin, sout, NN * CC);

        sin = sout;
    }
}

// round 6
// speedup vs baseline: 1.6428x; 1.1686x over previous
#include <cuda_runtime.h>
#include <cuda_bf16.h>
#include <mma.h>
#include <cstdint>
#include <math.h>

using namespace nvcuda;

#define NN 50000
#define CC 128
#define EE 800000
#define NPAD 50048            // 391 * 128

// ---------------- scratch (static device globals; no allocation) ----------
__device__ float g_sA[NN * CC];        // state ping
__device__ float g_sB[NN * CC];        // state pong
__device__ float g_gi[NPAD * 3 * CC];  // input gates (padded rows)
__device__ float g_gh[NPAD * 3 * CC];  // hidden gates (padded rows)
__device__ float g_wcomb[384 * CC];    // W_ih @ W_lin (fp32)
__device__ int   g_cnt[NN];
__device__ int   g_rowptr[NN + 1];
__device__ int   g_perm[EE];
__device__ int   g_bsum[64];

// bf16 split buffers (padded rows; pad region zeroed once)
__device__ __nv_bfloat16 g_sxh[NPAD * CC];   // state hi
__device__ __nv_bfloat16 g_sxl[NPAD * CC];   // state lo
__device__ __nv_bfloat16 g_sph[NPAD * CC];   // prop hi
__device__ __nv_bfloat16 g_spl[NPAD * CC];   // prop lo
__device__ __nv_bfloat16 g_wch[384 * CC];    // W_comb hi/lo
__device__ __nv_bfloat16 g_wcl[384 * CC];
__device__ __nv_bfloat16 g_whhh[384 * CC];   // W_hh hi/lo
__device__ __nv_bfloat16 g_whhl[384 * CC];

// ---------------- small utility kernels -----------------------------------
__global__ void zero_int(int* p, int n) {
    int i = blockIdx.x * blockDim.x + threadIdx.x;
    if (i < n) p[i] = 0;
}

__global__ void zero_pad_bf16(__nv_bfloat16* a, __nv_bfloat16* b,
                              __nv_bfloat16* c, __nv_bfloat16* d) {
    int i = blockIdx.x * blockDim.x + threadIdx.x;
    int n = (NPAD - NN) * CC;
    if (i < n) {
        int off = NN * CC + i;
        __nv_bfloat16 z = __float2bfloat16(0.f);
        a[off] = z; b[off] = z; c[off] = z; d[off] = z;
    }
}

__global__ void count_k(const int* __restrict__ dst, int* __restrict__ cnt) {
    int e = blockIdx.x * blockDim.x + threadIdx.x;
    if (e < EE) {
        int d = dst[e];
        d = min(max(d, 0), NN - 1);
        atomicAdd(&cnt[d], 1);
    }
}

__global__ void scan_block(const int* __restrict__ cnt, int* __restrict__ excl,
                           int* __restrict__ bsum, int n) {
    __shared__ int sm[1024];
    int t = threadIdx.x;
    int g = blockIdx.x * 1024 + t;
    int v = (g < n) ? cnt[g] : 0;
    sm[t] = v;
    __syncthreads();
    for (int off = 1; off < 1024; off <<= 1) {
        int tv = 0;
        if (t >= off) tv = sm[t - off];
        __syncthreads();
        if (t >= off) sm[t] += tv;
        __syncthreads();
    }
    if (g < n) excl[g] = sm[t] - v;
    if (t == 1023) bsum[blockIdx.x] = sm[1023];
}

__global__ void scan_sums(int* bsum, int nb) {
    int run = 0;
    for (int i = 0; i < nb; i++) { int t = bsum[i]; bsum[i] = run; run += t; }
}

__global__ void add_off(int* __restrict__ rowptr, const int* __restrict__ bsum, int n) {
    int g = blockIdx.x * blockDim.x + threadIdx.x;
    if (g < n) rowptr[g] += bsum[g >> 10];
    if (g == 0) rowptr[n] = EE;
}

__global__ void fill_k(const int* __restrict__ src, const int* __restrict__ dst,
                       const int* __restrict__ rowptr, int* __restrict__ cur,
                       int* __restrict__ perm) {
    int e = blockIdx.x * blockDim.x + threadIdx.x;
    if (e < EE) {
        int d = dst[e];
        d = min(max(d, 0), NN - 1);
        int s = src[e];
        s = min(max(s, 0), NN - 1);
        int pos = rowptr[d] + atomicAdd(&cur[d], 1);
        if (pos >= 0 && pos < EE) perm[pos] = s;
    }
}

// ---------------- W_comb = W_ih @ W_lin (fp32, once) -----------------------
__global__ void wcomb_k(const float* __restrict__ W_ih, const float* __restrict__ W_lin,
                        float* __restrict__ W_comb) {
    int i = blockIdx.x;     // 0..383
    int j = threadIdx.x;    // 0..127
    float s = 0.f;
    #pragma unroll 8
    for (int k = 0; k < 128; k++)
        s += W_ih[i * 128 + k] * W_lin[k * 128 + j];
    W_comb[i * 128 + j] = s;
}

// ---------------- fp32 -> bf16 hi/lo split ---------------------------------
__global__ void conv_split(const float* __restrict__ x, __nv_bfloat16* __restrict__ hi,
                           __nv_bfloat16* __restrict__ lo, int n4) {
    int i = blockIdx.x * blockDim.x + threadIdx.x;
    if (i >= n4) return;
    float4 v = ((const float4*)x)[i];
    __nv_bfloat16 h0 = __float2bfloat16(v.x);
    __nv_bfloat16 h1 = __float2bfloat16(v.y);
    __nv_bfloat16 h2 = __float2bfloat16(v.z);
    __nv_bfloat16 h3 = __float2bfloat16(v.w);
    __nv_bfloat16 l0 = __float2bfloat16(v.x - __bfloat162float(h0));
    __nv_bfloat16 l1 = __float2bfloat16(v.y - __bfloat162float(h1));
    __nv_bfloat16 l2 = __float2bfloat16(v.z - __bfloat162float(h2));
    __nv_bfloat16 l3 = __float2bfloat16(v.w - __bfloat162float(h3));
    __nv_bfloat162* hp = (__nv_bfloat162*)hi;
    __nv_bfloat162* lp = (__nv_bfloat162*)lo;
    hp[i * 2 + 0] = __nv_bfloat162(h0, h1);
    hp[i * 2 + 1] = __nv_bfloat162(h2, h3);
    lp[i * 2 + 0] = __nv_bfloat162(l0, l1);
    lp[i * 2 + 1] = __nv_bfloat162(l2, l3);
}

// ---------------- wmma split-bf16 GEMM --------------------------------------
// Y[NPAD, M] = A[NPAD,128] @ B[M,128]^T, A=Ah+Al, B=Bh+Bl (drop Al*Bl)
// block 128x64 tile, full K=128 in smem, 256 threads (8 warps 4x2),
// warp tile 32x32. 2 CTAs/SM.
#define LDSB 136                              // 128 + 8 bf16 pad
#define SM_A (128 * LDSB)
#define SM_B (64 * LDSB)
#define GT_SMEM ((2 * SM_A + 2 * SM_B) * 2)   // 104448 bytes

__global__ __launch_bounds__(256, 2)
void gemm_tc(const __nv_bfloat16* __restrict__ Ah, const __nv_bfloat16* __restrict__ Al,
             const __nv_bfloat16* __restrict__ Bh, const __nv_bfloat16* __restrict__ Bl,
             float* __restrict__ Y, int M) {
    extern __shared__ __nv_bfloat16 smb[];
    __nv_bfloat16* As_h = smb;
    __nv_bfloat16* As_l = smb + SM_A;
    __nv_bfloat16* Bs_h = smb + 2 * SM_A;
    __nv_bfloat16* Bs_l = smb + 2 * SM_A + SM_B;

    int row0 = blockIdx.x * 128;
    int col0 = blockIdx.y * 64;
    int t = threadIdx.x;

    // A tiles: 128 rows x 16 uint4 each = 2048 uint4; 8 per thread per tile
    {
        const uint4* gAh = (const uint4*)(Ah + (size_t)row0 * 128);
        const uint4* gAl = (const uint4*)(Al + (size_t)row0 * 128);
        #pragma unroll
        for (int i = 0; i < 8; i++) {
            int idx = t + i * 256;
            int r = idx >> 4;
            int c = idx & 15;
            ((uint4*)(As_h + r * LDSB))[c] = gAh[r * 16 + c];
            ((uint4*)(As_l + r * LDSB))[c] = gAl[r * 16 + c];
        }
    }
    // B tiles: 64 rows x 16 uint4 = 1024 uint4; 4 per thread per tile
    {
        const uint4* gBh = (const uint4*)(Bh + (size_t)col0 * 128);
        const uint4* gBl = (const uint4*)(Bl + (size_t)col0 * 128);
        #pragma unroll
        for (int i = 0; i < 4; i++) {
            int idx = t + i * 256;
            int r = idx >> 4;
            int c = idx & 15;
            ((uint4*)(Bs_h + r * LDSB))[c] = gBh[r * 16 + c];
            ((uint4*)(Bs_l + r * LDSB))[c] = gBl[r * 16 + c];
        }
    }
    __syncthreads();

    int wid = t >> 5;
    int wm = wid >> 1;      // 0..3 -> 32-row slabs
    int wn = wid & 1;       // 0..1 -> 32-col slabs

    wmma::fragment<wmma::accumulator, 16, 16, 16, float> acc[2][2];
    #pragma unroll
    for (int i = 0; i < 2; i++)
        #pragma unroll
        for (int j = 0; j < 2; j++) wmma::fill_fragment(acc[i][j], 0.0f);

    #pragma unroll
    for (int ks = 0; ks < 8; ks++) {
        int k0 = ks * 16;
        wmma::fragment<wmma::matrix_a, 16, 16, 16, __nv_bfloat16, wmma::row_major> ah[2], al[2];
        wmma::fragment<wmma::matrix_b, 16, 16, 16, __nv_bfloat16, wmma::col_major> bh[2], bl[2];
        #pragma unroll
        for (int i = 0; i < 2; i++) {
            int rr = wm * 32 + i * 16;
            wmma::load_matrix_sync(ah[i], &As_h[rr * LDSB + k0], LDSB);
            wmma::load_matrix_sync(al[i], &As_l[rr * LDSB + k0], LDSB);
        }
        #pragma unroll
        for (int j = 0; j < 2; j++) {
            int cc = wn * 32 + j * 16;
            wmma::load_matrix_sync(bh[j], &Bs_h[cc * LDSB + k0], LDSB);
            wmma::load_matrix_sync(bl[j], &Bs_l[cc * LDSB + k0], LDSB);
        }
        #pragma unroll
        for (int i = 0; i < 2; i++) {
            #pragma unroll
            for (int j = 0; j < 2; j++) {
                wmma::mma_sync(acc[i][j], ah[i], bh[j], acc[i][j]);
                wmma::mma_sync(acc[i][j], ah[i], bl[j], acc[i][j]);
                wmma::mma_sync(acc[i][j], al[i], bh[j], acc[i][j]);
            }
        }
    }

    #pragma unroll
    for (int i = 0; i < 2; i++) {
        #pragma unroll
        for (int j = 0; j < 2; j++) {
            size_t off = (size_t)(row0 + wm * 32 + i * 16) * M + col0 + wn * 32 + j * 16;
            wmma::store_matrix_sync(&Y[off], acc[i][j], M, wmma::mem_row_major);
        }
    }
}

// ---------------- aggregation: prop[i,:] = sum in-edges state[src,:] -------
// writes bf16 hi/lo split directly (GEMM consumes it)
__global__ void aggregate(const float* __restrict__ st, const int* __restrict__ rowptr,
                          const int* __restrict__ perm,
                          __nv_bfloat16* __restrict__ ph, __nv_bfloat16* __restrict__ pl) {
    int i = blockIdx.x;
    int c = threadIdx.x;
    int s0 = rowptr[i], s1 = rowptr[i + 1];
    float a0 = 0.f, a1 = 0.f, a2 = 0.f, a3 = 0.f;
    int e = s0;
    for (; e + 3 < s1; e += 4) {
        int p0 = perm[e], p1 = perm[e + 1], p2 = perm[e + 2], p3 = perm[e + 3];
        a0 += st[p0 * 128 + c];
        a1 += st[p1 * 128 + c];
        a2 += st[p2 * 128 + c];
        a3 += st[p3 * 128 + c];
    }
    for (; e < s1; e++) a0 += st[perm[e] * 128 + c];
    float s = (a0 + a1) + (a2 + a3);
    __nv_bfloat16 h = __float2bfloat16(s);
    ph[i * 128 + c] = h;
    pl[i * 128 + c] = __float2bfloat16(s - __bfloat162float(h));
}

// ---------------- GRU elementwise (biases here; emits fp32 + bf16 split) ---
__global__ void gru_k(const float* __restrict__ gi, const float* __restrict__ gh,
                      const float* __restrict__ b_ih, const float* __restrict__ b_hh,
                      const float* __restrict__ h, float* __restrict__ out,
                      __nv_bfloat16* __restrict__ oh, __nv_bfloat16* __restrict__ ol,
                      int n) {
    int idx = blockIdx.x * blockDim.x + threadIdx.x;
    if (idx >= n) return;
    int i = idx >> 7;
    int c = idx & 127;
    const float* gir = gi + (size_t)i * 384;
    const float* ghr = gh + (size_t)i * 384;
    float ir = gir[c] + b_ih[c];
    float iz = gir[c + 128] + b_ih[c + 128];
    float in_ = gir[c + 256] + b_ih[c + 256];
    float hr = ghr[c] + b_hh[c];
    float hz = ghr[c + 128] + b_hh[c + 128];
    float hn = ghr[c + 256] + b_hh[c + 256];
    float r = 1.f / (1.f + expf(-(ir + hr)));
    float z = 1.f / (1.f + expf(-(iz + hz)));
    float nval = tanhf(in_ + r * hn);
    float val = (1.f - z) * nval + z * h[idx];
    out[idx] = val;
    __nv_bfloat16 vh = __float2bfloat16(val);
    oh[idx] = vh;
    ol[idx] = __float2bfloat16(val - __bfloat162float(vh));
}

// ---------------- launcher --------------------------------------------------
extern "C" void kernel_launch(void* const* d_in, const int* in_sizes, int n_in,
                              void* d_out, int out_size) {
    const float* x     = (const float*)d_in[0];
    const int*   ei    = (const int*)d_in[1];   // int32 (JAX x64 disabled)
    const float* W_lin = (const float*)d_in[2];
    const float* W_ih  = (const float*)d_in[3];
    const float* W_hh  = (const float*)d_in[4];
    const float* b_ih  = (const float*)d_in[5];
    const float* b_hh  = (const float*)d_in[6];
    float* out = (float*)d_out;

    const int* src = ei;
    const int* dst = ei + EE;

    float *sA_, *sB_, *gi_, *gh_, *wc_;
    int *cnt_, *rp_, *perm_, *bsum_;
    __nv_bfloat16 *sxh_, *sxl_, *sph_, *spl_, *wch_, *wcl_, *whhh_, *whhl_;
    cudaGetSymbolAddress((void**)&sA_,   g_sA);
    cudaGetSymbolAddress((void**)&sB_,   g_sB);
    cudaGetSymbolAddress((void**)&gi_,   g_gi);
    cudaGetSymbolAddress((void**)&gh_,   g_gh);
    cudaGetSymbolAddress((void**)&wc_,   g_wcomb);
    cudaGetSymbolAddress((void**)&cnt_,  g_cnt);
    cudaGetSymbolAddress((void**)&rp_,   g_rowptr);
    cudaGetSymbolAddress((void**)&perm_, g_perm);
    cudaGetSymbolAddress((void**)&bsum_, g_bsum);
    cudaGetSymbolAddress((void**)&sxh_,  g_sxh);
    cudaGetSymbolAddress((void**)&sxl_,  g_sxl);
    cudaGetSymbolAddress((void**)&sph_,  g_sph);
    cudaGetSymbolAddress((void**)&spl_,  g_spl);
    cudaGetSymbolAddress((void**)&wch_,  g_wch);
    cudaGetSymbolAddress((void**)&wcl_,  g_wcl);
    cudaGetSymbolAddress((void**)&whhh_, g_whhh);
    cudaGetSymbolAddress((void**)&whhl_, g_whhl);

    cudaFuncSetAttribute(gemm_tc, cudaFuncAttributeMaxDynamicSharedMemorySize, GT_SMEM);

    const int NB_SCAN = (NN + 1023) / 1024;   // 49
    const int N4 = NN * CC / 4;
    const dim3 gg(NPAD / 128, 384 / 64);      // 391 x 6

    // 1: W_comb = W_ih @ W_lin
    wcomb_k<<<384, 128>>>(W_ih, W_lin, wc_);
    // 2,3: split weights
    conv_split<<<(384 * CC / 4 + 255) / 256, 256>>>(wc_, wch_, wcl_, 384 * CC / 4);
    conv_split<<<(384 * CC / 4 + 255) / 256, 256>>>(W_hh, whhh_, whhl_, 384 * CC / 4);
    // 4: zero pad rows of split activation buffers
    zero_pad_bf16<<<((NPAD - NN) * CC + 255) / 256, 256>>>(sxh_, sxl_, sph_, spl_);
    // 5: split x
    conv_split<<<(N4 + 255) / 256, 256>>>(x, sxh_, sxl_, N4);
    // 6: gh for step 0  (this is the ncu-profiled launch: -s 5 -c 1)
    gemm_tc<<<gg, 256, GT_SMEM>>>(sxh_, sxl_, whhh_, whhl_, gh_, 384);

    // ---- build CSR ----
    zero_int <<<(NN + 255) / 256, 256>>>(cnt_, NN);
    count_k  <<<(EE + 255) / 256, 256>>>(dst, cnt_);
    scan_block<<<NB_SCAN, 1024>>>(cnt_, rp_, bsum_, NN);
    scan_sums <<<1, 1>>>(bsum_, NB_SCAN);
    add_off   <<<(NN + 255) / 256, 256>>>(rp_, bsum_, NN);
    zero_int  <<<(NN + 255) / 256, 256>>>(cnt_, NN);
    fill_k    <<<(EE + 255) / 256, 256>>>(src, dst, rp_, cnt_, perm_);

    // ---- 3 propagation steps ----
    const float* sin = x;
    for (int step = 0; step < 3; step++) {
        float* sout = (step == 2) ? out : ((step == 0) ? sA_ : sB_);

        if (step > 0)   // step 0's gh was computed above
            gemm_tc<<<gg, 256, GT_SMEM>>>(sxh_, sxl_, whhh_, whhl_, gh_, 384);
        aggregate<<<NN, 128>>>(sin, rp_, perm_, sph_, spl_);
        gemm_tc<<<gg, 256, GT_SMEM>>>(sph_, spl_, wch_, wcl_, gi_, 384);
        gru_k<<<(NN * CC + 255) / 256, 256>>>(gi_, gh_, b_ih, b_hh, sin, sout,
                                              sxh_, sxl_, NN * CC);
        sin = sout;
    }
}